// round 1
// baseline (speedup 1.0000x reference)
#include <cuda_runtime.h>
#include <stdint.h>

// TorchNeighborList on GB300.
// Structure: output = stable counting sort (by atom index, valid-first) of the
// bidirectional pair list. Valid pairs are sparse (~20K / 28.3M) so:
//   pass1: validity bitmask + per-tile counts + per-atom valid-bucket append
//   scan : exclusive scans (tiles -> invalid ranks, atoms -> valid ranks), total V
//   writeValid: scatter ~20K valid records (rank within atom = #smaller t in bucket)
//   writeInvalid: bulk 680MB write; rank = V + t - validBefore(t) from bitmask popcounts

#define NA      1024
#define NM1     1023
#define PC      523776LL          // NA*(NA-1)/2
#define TILE    8192
#define WPT     256               // 32-bit mask words per tile
#define MAXB    256               // per-atom valid bucket capacity (expected ~20)
#define CUT     5.0f

__device__ unsigned d_mask[900000];     // (2P+31)/32 = 884,704 words used
__device__ int      d_tileCounts[4096];
__device__ int      d_tileOffsets[4096];
__device__ int      d_atomCount[NA];
__device__ int      d_atomBase[NA];
__device__ unsigned d_bucket[NA * MAXB];
__device__ int      d_V;

__device__ __forceinline__ long long rowstart(int i) {
    // triu_indices(N, k=1): row i starts at i*(N-1) - i*(i-1)/2
    return (long long)i * NM1 - ((long long)i * (i - 1)) / 2;
}

// Decode half-index t2 in [0, P) -> (i0, j0, shift index s; s = -1 for center pairs)
__device__ __forceinline__ void decodeIdx(long long t2, int& i0, int& j0, int& s) {
    if (t2 < PC) {
        s = -1;
        double a = 1023.5;
        double q = (double)t2;
        int i = (int)(a - sqrt(a * a - 2.0 * q));
        if (i < 0) i = 0;
        if (i > 1022) i = 1022;
        while (rowstart(i + 1) <= t2) ++i;
        while (rowstart(i) > t2) --i;
        i0 = i;
        j0 = (int)(t2 - rowstart(i)) + i + 1;
    } else {
        long long u = t2 - PC;
        s = (int)(u >> 20);            // N*N = 2^20
        int rem = (int)(u & 0xFFFFF);
        i0 = rem >> 10;                // N = 2^10
        j0 = rem & 1023;
    }
}

__global__ void initK() {
    d_atomCount[threadIdx.x] = 0;
}

__global__ void pass1(const float* __restrict__ pos, const float* __restrict__ box,
                      const int* __restrict__ shifts, int S, long long P, long long TWOP) {
    __shared__ float spx[NA], spy[NA], spz[NA];
    __shared__ float svx[32], svy[32], svz[32];
    __shared__ int warpCnt[8];
    int tid = threadIdx.x;
    for (int k = tid; k < NA; k += blockDim.x) {
        spx[k] = pos[3 * k + 0];
        spy[k] = pos[3 * k + 1];
        spz[k] = pos[3 * k + 2];
    }
    if (tid < S) {
        float s0 = (float)shifts[3 * tid + 0];
        float s1 = (float)shifts[3 * tid + 1];
        float s2 = (float)shifts[3 * tid + 2];
        svx[tid] = s0 * box[0] + s1 * box[3] + s2 * box[6];
        svy[tid] = s0 * box[1] + s1 * box[4] + s2 * box[7];
        svz[tid] = s0 * box[2] + s1 * box[5] + s2 * box[8];
    }
    if (tid < 8) warpCnt[tid] = 0;
    __syncthreads();

    long long tileStart = (long long)blockIdx.x * TILE;
    int lane = tid & 31, wid = tid >> 5;
    int myCnt = 0;

    #pragma unroll 1
    for (int c = 0; c < 32; c++) {
        long long t = tileStart + (long long)c * 256 + tid;
        bool valid = false;
        int bi = 0;
        if (t < TWOP) {
            bool second = t >= P;
            long long t2 = second ? t - P : t;
            int i0, j0, s;
            decodeIdx(t2, i0, j0, s);
            // IEEE f32, fma-free, fixed order: ((pi - pj) + sv), x^2 + y^2 + z^2, sqrt
            float dx = __fsub_rn(spx[i0], spx[j0]);
            float dy = __fsub_rn(spy[i0], spy[j0]);
            float dz = __fsub_rn(spz[i0], spz[j0]);
            if (s >= 0) {
                dx = __fadd_rn(dx, svx[s]);
                dy = __fadd_rn(dy, svy[s]);
                dz = __fadd_rn(dz, svz[s]);
            }
            float r2 = __fadd_rn(__fadd_rn(__fmul_rn(dx, dx), __fmul_rn(dy, dy)),
                                 __fmul_rn(dz, dz));
            float d = __fsqrt_rn(r2);
            valid = d < CUT;
            bi = second ? j0 : i0;
        }
        unsigned b = __ballot_sync(0xFFFFFFFFu, valid);
        if (lane == 0) {
            d_mask[(int)(tileStart >> 5) + c * 8 + wid] = b;
            myCnt += __popc(b);
        }
        if (valid) {
            int slot = atomicAdd(&d_atomCount[bi], 1);
            if (slot < MAXB) d_bucket[bi * MAXB + slot] = (unsigned)t;
        }
    }
    if (lane == 0) warpCnt[wid] = myCnt;
    __syncthreads();
    if (tid == 0) {
        int s = 0;
        for (int w = 0; w < 8; w++) s += warpCnt[w];
        d_tileCounts[blockIdx.x] = s;
    }
}

__global__ void scanK(int numTiles) {
    __shared__ int sh[1024];
    int tid = threadIdx.x;
    int carry = 0;
    for (int base = 0; base < numTiles; base += 1024) {
        int idx = base + tid;
        int v = (idx < numTiles) ? d_tileCounts[idx] : 0;
        sh[tid] = v;
        __syncthreads();
        for (int off = 1; off < 1024; off <<= 1) {
            int x = (tid >= off) ? sh[tid - off] : 0;
            __syncthreads();
            sh[tid] += x;
            __syncthreads();
        }
        if (idx < numTiles) d_tileOffsets[idx] = carry + sh[tid] - v;
        int tot = sh[1023];
        __syncthreads();
        carry += tot;
    }
    if (tid == 0) d_V = carry;
    // atom exclusive scan (valid region starts at 0)
    int v = d_atomCount[tid];
    sh[tid] = v;
    __syncthreads();
    for (int off = 1; off < 1024; off <<= 1) {
        int x = (tid >= off) ? sh[tid - off] : 0;
        __syncthreads();
        sh[tid] += x;
        __syncthreads();
    }
    d_atomBase[tid] = sh[tid] - v;
}

__global__ void writeValid(const float* __restrict__ box, const int* __restrict__ shifts,
                           long long P, long long TWOP, float* __restrict__ out) {
    __shared__ unsigned sb[MAXB];
    int v = blockIdx.x;
    int c = d_atomCount[v];
    if (c > MAXB) c = MAXB;
    int tid = threadIdx.x;
    for (int k = tid; k < c; k += blockDim.x) sb[k] = d_bucket[v * MAXB + k];
    __syncthreads();
    if (tid >= c) return;
    unsigned te = sb[tid];
    int rank = 0;
    for (int k = 0; k < c; k++) rank += (sb[k] < te) ? 1 : 0;
    long long r = (long long)d_atomBase[v] + rank;

    long long t = (long long)te;
    bool second = t >= P;
    long long t2 = second ? t - P : t;
    int i0, j0, s;
    decodeIdx(t2, i0, j0, s);
    int bi = second ? j0 : i0;
    int bj = second ? i0 : j0;
    float o0 = 0.f, o1 = 0.f, o2 = 0.f;
    if (s >= 0) {
        float sgn = second ? 1.0f : -1.0f;   // -shifts first half, +shifts second half
        float s0 = sgn * (float)shifts[3 * s + 0];
        float s1 = sgn * (float)shifts[3 * s + 1];
        float s2 = sgn * (float)shifts[3 * s + 2];
        o0 = s0 * box[0] + s1 * box[3] + s2 * box[6];
        o1 = s0 * box[1] + s1 * box[4] + s2 * box[7];
        o2 = s0 * box[2] + s1 * box[5] + s2 * box[8];
    }
    out[r] = (float)bi;
    out[TWOP + r] = (float)bj;
    long long ob = 2 * TWOP + 3 * r;
    out[ob + 0] = o0;
    out[ob + 1] = o1;
    out[ob + 2] = o2;
    out[5 * TWOP + r] = 1.0f;
}

__global__ void writeInvalid(long long P, long long TWOP, float* __restrict__ out) {
    __shared__ unsigned words[WPT];
    __shared__ int ws[WPT];
    int tid = threadIdx.x;
    long long tileStart = (long long)blockIdx.x * TILE;
    int wbase = blockIdx.x * WPT;
    unsigned w = d_mask[wbase + tid];
    words[tid] = w;
    ws[tid] = __popc(w);
    __syncthreads();
    for (int off = 1; off < WPT; off <<= 1) {
        int x = (tid >= off) ? ws[tid - off] : 0;
        __syncthreads();
        ws[tid] += x;
        __syncthreads();
    }
    int tileOff = d_tileOffsets[blockIdx.x];
    int V = d_V;

    #pragma unroll 1
    for (int c = 0; c < 32; c++) {
        long long t = tileStart + (long long)c * 256 + tid;
        if (t < TWOP) {
            int widx = c * 8 + (tid >> 5);
            unsigned word = words[widx];
            unsigned bit = (word >> (tid & 31)) & 1u;
            if (!bit) {
                int vb = (ws[widx] - __popc(word)) +
                         __popc(word & ((1u << (tid & 31)) - 1u));
                long long r = (long long)V + t - (long long)(tileOff + vb);
                bool second = t >= P;
                long long t2 = second ? t - P : t;
                int i0, j0, s;
                decodeIdx(t2, i0, j0, s);
                int bi = second ? j0 : i0;
                int bj = second ? i0 : j0;
                out[r] = (float)bi;
                out[TWOP + r] = (float)bj;
                long long ob = 2 * TWOP + 3 * r;
                out[ob + 0] = 0.f;
                out[ob + 1] = 0.f;
                out[ob + 2] = 0.f;
                out[5 * TWOP + r] = 0.f;
            }
        }
    }
}

extern "C" void kernel_launch(void* const* d_in, const int* in_sizes, int n_in,
                              void* d_out, int out_size) {
    const float* pos   = (const float*)d_in[0];
    const float* box   = (const float*)d_in[1];
    const int* shifts  = (const int*)d_in[2];
    int S = in_sizes[2] / 3;

    long long TWOP = (long long)out_size / 6;   // 28,310,528
    long long P = TWOP / 2;
    int numTiles = (int)((TWOP + TILE - 1) / TILE);

    initK<<<1, NA>>>();
    pass1<<<numTiles, 256>>>(pos, box, shifts, S, P, TWOP);
    scanK<<<1, 1024>>>(numTiles);
    writeValid<<<NA, 256>>>(box, shifts, P, TWOP, (float*)d_out);
    writeInvalid<<<numTiles, 256>>>(P, TWOP, (float*)d_out);
}

// round 2
// speedup vs baseline: 1.5780x; 1.5780x over previous
#include <cuda_runtime.h>
#include <stdint.h>

// TorchNeighborList on GB300 — R2.
// Output = stable counting sort (by atom idx, valid-first) of bidirectional pairs.
// Key facts exploited:
//   * second half of bidirectional list has IDENTICAL distances -> compute P not 2P
//   * invalid region (>99.9%) has zero offsets/valid -> bulk float4 zero-fill
//   * rank of invalid entry t = V + t - validBefore(t), validBefore from a
//     two-level popcount scan over the validity bitmask (no per-tile coupling)

#define NA    1024
#define PCI   523776            // NA*(NA-1)/2, divisible by 32
#define MAXB  256
#define CUT   5.0f

__device__ unsigned d_mask[442368];     // P/32 = 442,352 words used
__device__ int      d_wpre[442368];     // exclusive popc prefix within 1024-word block
__device__ int      d_bsums[512];
__device__ int      d_bpre[512];
__device__ int      d_atomCount[NA];
__device__ int      d_atomBase[NA];
__device__ unsigned d_bucket[NA * MAXB];
__device__ int      d_Vh;               // valid count in first half
__device__ int      d_V;                // total valid = 2*Vh

__device__ __forceinline__ int rowstartC(int i) {
    return i * 1023 - (i * (i - 1)) / 2;   // triu row start, fits int
}

// center-pair decode, exact-float sqrt + integer correction
__device__ __forceinline__ void decodeCenter(int t2, int& i0, int& j0) {
    float q = (float)t2;
    float disc = __fsub_rn(1047552.25f, __fadd_rn(q, q));  // 1023.5^2 - 2q, exact
    int i = (int)(1023.5f - __fsqrt_rn(disc));
    if (i < 0) i = 0;
    if (i > 1022) i = 1022;
    while (rowstartC(i + 1) <= t2) ++i;
    while (rowstartC(i) > t2) --i;
    i0 = i;
    j0 = t2 - rowstartC(i) + i + 1;
}

__global__ void initK() { d_atomCount[threadIdx.x] = 0; }

// ---- pass1 over outside region rows: block = 8 rows of 1024 j's ----
__global__ void pass1_outside(const float* __restrict__ pos, const float* __restrict__ box,
                              const int* __restrict__ shifts, long long P) {
    __shared__ float spx[NA], spy[NA], spz[NA];
    int tid = threadIdx.x;
    for (int k = tid; k < NA; k += 256) {
        spx[k] = pos[3 * k + 0];
        spy[k] = pos[3 * k + 1];
        spz[k] = pos[3 * k + 2];
    }
    __syncthreads();
    int rowBase = blockIdx.x * 8;
    #pragma unroll 1
    for (int rr = 0; rr < 8; rr++) {
        int row = rowBase + rr;
        int s = row >> 10, i = row & 1023;
        float s0 = (float)shifts[3 * s + 0];
        float s1 = (float)shifts[3 * s + 1];
        float s2 = (float)shifts[3 * s + 2];
        float svx = s0 * box[0] + s1 * box[3] + s2 * box[6];
        float svy = s0 * box[1] + s1 * box[4] + s2 * box[7];
        float svz = s0 * box[2] + s1 * box[5] + s2 * box[8];
        float pix = spx[i], piy = spy[i], piz = spz[i];
        int t2base = PCI + (row << 10);
        #pragma unroll
        for (int c = 0; c < 4; c++) {
            int j = c * 256 + tid;
            float dx = __fadd_rn(__fsub_rn(pix, spx[j]), svx);
            float dy = __fadd_rn(__fsub_rn(piy, spy[j]), svy);
            float dz = __fadd_rn(__fsub_rn(piz, spz[j]), svz);
            float r2 = __fadd_rn(__fadd_rn(__fmul_rn(dx, dx), __fmul_rn(dy, dy)),
                                 __fmul_rn(dz, dz));
            bool valid = __fsqrt_rn(r2) < CUT;
            unsigned b = __ballot_sync(0xFFFFFFFFu, valid);
            if ((tid & 31) == 0)
                d_mask[(t2base >> 5) + c * 8 + (tid >> 5)] = b;
            if (valid) {
                unsigned t2 = (unsigned)(t2base + j);
                int sl = atomicAdd(&d_atomCount[i], 1);
                if (sl < MAXB) d_bucket[i * MAXB + sl] = t2;
                int s2a = atomicAdd(&d_atomCount[j], 1);
                if (s2a < MAXB) d_bucket[j * MAXB + s2a] = t2 + (unsigned)P;
            }
        }
    }
}

// ---- pass1 over center pairs (t2 < PCI) ----
__global__ void pass1_center(const float* __restrict__ pos, long long P) {
    __shared__ float spx[NA], spy[NA], spz[NA];
    int tid = threadIdx.x;
    for (int k = tid; k < NA; k += 256) {
        spx[k] = pos[3 * k + 0];
        spy[k] = pos[3 * k + 1];
        spz[k] = pos[3 * k + 2];
    }
    __syncthreads();
    #pragma unroll 1
    for (int c = 0; c < 32; c++) {
        int t2 = blockIdx.x * 8192 + c * 256 + tid;
        bool valid = false;
        int i0 = 0, j0 = 0;
        if (t2 < PCI) {
            decodeCenter(t2, i0, j0);
            float dx = __fsub_rn(spx[i0], spx[j0]);
            float dy = __fsub_rn(spy[i0], spy[j0]);
            float dz = __fsub_rn(spz[i0], spz[j0]);
            float r2 = __fadd_rn(__fadd_rn(__fmul_rn(dx, dx), __fmul_rn(dy, dy)),
                                 __fmul_rn(dz, dz));
            valid = __fsqrt_rn(r2) < CUT;
        }
        unsigned b = __ballot_sync(0xFFFFFFFFu, valid);
        int wb = blockIdx.x * 256 + c * 8 + (tid >> 5);
        if ((tid & 31) == 0 && wb < (PCI >> 5))
            d_mask[wb] = b;
        if (valid) {
            int sl = atomicAdd(&d_atomCount[i0], 1);
            if (sl < MAXB) d_bucket[i0 * MAXB + sl] = (unsigned)t2;
            int s2a = atomicAdd(&d_atomCount[j0], 1);
            if (s2a < MAXB) d_bucket[j0 * MAXB + s2a] = (unsigned)(t2 + P);
        }
    }
}

// ---- two-level popcount scan over mask words ----
__global__ void scanA(int W) {
    __shared__ int sh[1024];
    int tid = threadIdx.x;
    int w = blockIdx.x * 1024 + tid;
    int v = (w < W) ? __popc(d_mask[w]) : 0;
    sh[tid] = v;
    __syncthreads();
    for (int off = 1; off < 1024; off <<= 1) {
        int x = (tid >= off) ? sh[tid - off] : 0;
        __syncthreads();
        sh[tid] += x;
        __syncthreads();
    }
    if (w < W) d_wpre[w] = sh[tid] - v;
    if (tid == 1023) d_bsums[blockIdx.x] = sh[1023];
}

__global__ void scanB(int nb) {
    __shared__ int sh[1024];
    int tid = threadIdx.x;
    int v = (tid < nb) ? d_bsums[tid] : 0;
    sh[tid] = v;
    __syncthreads();
    for (int off = 1; off < 1024; off <<= 1) {
        int x = (tid >= off) ? sh[tid - off] : 0;
        __syncthreads();
        sh[tid] += x;
        __syncthreads();
    }
    if (tid < nb) d_bpre[tid] = sh[tid] - v;
    if (tid == 1023) { d_Vh = sh[1023]; d_V = 2 * sh[1023]; }
    __syncthreads();
    int a = d_atomCount[tid];
    sh[tid] = a;
    __syncthreads();
    for (int off = 1; off < 1024; off <<= 1) {
        int x = (tid >= off) ? sh[tid - off] : 0;
        __syncthreads();
        sh[tid] += x;
        __syncthreads();
    }
    d_atomBase[tid] = sh[tid] - a;
}

// ---- zero-fill offsets + valid regions with float4 ----
__global__ void zeroFill(float4* __restrict__ p, long long n) {
    long long stride = (long long)gridDim.x * blockDim.x;
    float4 z = make_float4(0.f, 0.f, 0.f, 0.f);
    for (long long i = (long long)blockIdx.x * blockDim.x + threadIdx.x; i < n; i += stride)
        p[i] = z;
}

// ---- idx_i / idx_j for all invalid entries ----
__global__ void writeIdx(long long P, long long TWOP, float* __restrict__ out) {
    long long stride = (long long)gridDim.x * blockDim.x;
    int V = d_V, Vh = d_Vh;
    for (long long t = (long long)blockIdx.x * blockDim.x + threadIdx.x; t < TWOP; t += stride) {
        bool second = t >= P;
        int t2 = (int)(second ? t - P : t);
        unsigned w = (unsigned)t2 >> 5;
        unsigned word = d_mask[w];
        unsigned lanebit = 1u << (t2 & 31);
        if (word & lanebit) continue;   // valid: handled by writeValid
        int before = d_bpre[w >> 10] + d_wpre[w] + __popc(word & (lanebit - 1u));
        long long vb = second ? (long long)(Vh + before) : (long long)before;
        long long r = (long long)V + t - vb;
        int bi, bj;
        if (t2 >= PCI) {
            unsigned u = (unsigned)(t2 - PCI);
            bi = (int)((u >> 10) & 1023u);
            bj = (int)(u & 1023u);
        } else {
            decodeCenter(t2, bi, bj);
        }
        if (second) { int tmp = bi; bi = bj; bj = tmp; }
        out[r] = (float)bi;
        out[TWOP + r] = (float)bj;
    }
}

// ---- scatter the ~20K valid records ----
__global__ void writeValid(const float* __restrict__ box, const int* __restrict__ shifts,
                           long long P, long long TWOP, float* __restrict__ out) {
    __shared__ unsigned sb[MAXB];
    int v = blockIdx.x;
    int c = d_atomCount[v];
    if (c > MAXB) c = MAXB;
    int tid = threadIdx.x;
    for (int k = tid; k < c; k += blockDim.x) sb[k] = d_bucket[v * MAXB + k];
    __syncthreads();
    if (tid >= c) return;
    unsigned te = sb[tid];
    int rank = 0;
    for (int k = 0; k < c; k++) rank += (sb[k] < te) ? 1 : 0;
    long long r = (long long)d_atomBase[v] + rank;

    long long t = (long long)te;
    bool second = t >= P;
    int t2 = (int)(second ? t - P : t);
    int i0, j0, s;
    if (t2 >= PCI) {
        unsigned u = (unsigned)(t2 - PCI);
        s = (int)(u >> 20);
        i0 = (int)((u >> 10) & 1023u);
        j0 = (int)(u & 1023u);
    } else {
        s = -1;
        decodeCenter(t2, i0, j0);
    }
    int bi = second ? j0 : i0;
    int bj = second ? i0 : j0;
    float o0 = 0.f, o1 = 0.f, o2 = 0.f;
    if (s >= 0) {
        float sgn = second ? 1.0f : -1.0f;   // -shifts first half, +shifts second half
        float s0 = sgn * (float)shifts[3 * s + 0];
        float s1 = sgn * (float)shifts[3 * s + 1];
        float s2 = sgn * (float)shifts[3 * s + 2];
        o0 = s0 * box[0] + s1 * box[3] + s2 * box[6];
        o1 = s0 * box[1] + s1 * box[4] + s2 * box[7];
        o2 = s0 * box[2] + s1 * box[5] + s2 * box[8];
    }
    out[r] = (float)bi;
    out[TWOP + r] = (float)bj;
    long long ob = 2 * TWOP + 3 * r;
    out[ob + 0] = o0;
    out[ob + 1] = o1;
    out[ob + 2] = o2;
    out[5 * TWOP + r] = 1.0f;
}

extern "C" void kernel_launch(void* const* d_in, const int* in_sizes, int n_in,
                              void* d_out, int out_size) {
    const float* pos  = (const float*)d_in[0];
    const float* box  = (const float*)d_in[1];
    const int* shifts = (const int*)d_in[2];
    int S = in_sizes[2] / 3;                     // 13

    long long TWOP = (long long)out_size / 6;    // 28,310,528
    long long P = TWOP / 2;                      // 14,155,264
    int W = (int)(P / 32);                       // 442,352
    int nScanBlocks = (W + 1023) / 1024;         // 433
    float* out = (float*)d_out;

    initK<<<1, NA>>>();
    pass1_outside<<<S * NA / 8, 256>>>(pos, box, shifts, P);
    pass1_center<<<(PCI + 8191) / 8192, 256>>>(pos, P);
    scanA<<<nScanBlocks, 1024>>>(W);
    scanB<<<1, 1024>>>(nScanBlocks);
    // zero offsets [2*TWOP, 5*TWOP) + valid [5*TWOP, 6*TWOP) = TWOP float4s
    zeroFill<<<4736, 256>>>((float4*)(out + 2 * TWOP), TWOP);
    writeIdx<<<6912, 256>>>(P, TWOP, out);
    writeValid<<<NA, 256>>>(box, shifts, P, TWOP, out);
}

// round 5
// speedup vs baseline: 1.8419x; 1.1673x over previous
#include <cuda_runtime.h>
#include <stdint.h>

// TorchNeighborList on GB300 — R4 (R3 resubmit after infra failure).
// Output = stable counting sort (by atom idx, valid-first) of bidirectional pairs.
//   * distances computed once (P, not 2P); second-half rank = r1 + (P - Vh)
//   * single fused bulk kernel: zero-fill (453MB) + idx writes (226MB) + valid scatter
//   * shuffle-based two-level popcount scan over the validity bitmask

#define NA    1024
#define PCI   523776            // NA*(NA-1)/2
#define MAXB  256
#define CUT   5.0f
#define NZ    2560              // zero-fill blocks
#define NI    1792              // idx-writer blocks
#define OUTB  1664              // outside-region pass1 blocks (13*1024/8)
#define CTRB  64                // center-region pass1 blocks

__device__ unsigned d_mask[442368];     // P/32 = 442,352 words used
__device__ int      d_wpre[442368];
__device__ int      d_bsums[512];
__device__ int      d_bpre[512];
__device__ int      d_atomCount[NA];
__device__ int      d_atomBase[NA];
__device__ unsigned d_bucket[NA * MAXB];
__device__ int      d_Vh;               // valid count in first half
__device__ int      d_V;                // total valid = 2*Vh

__device__ __forceinline__ int rowstartC(int i) {
    return i * 1023 - (i * (i - 1)) / 2;
}

__device__ __forceinline__ void decodeCenter(int t2, int& i0, int& j0) {
    float q = (float)t2;
    float disc = __fsub_rn(1047552.25f, __fadd_rn(q, q));
    int i = (int)(1023.5f - __fsqrt_rn(disc));
    if (i < 0) i = 0;
    if (i > 1022) i = 1022;
    while (rowstartC(i + 1) <= t2) ++i;
    while (rowstartC(i) > t2) --i;
    i0 = i;
    j0 = t2 - rowstartC(i) + i + 1;
}

__global__ void initK() { d_atomCount[threadIdx.x] = 0; }

// ---- pass1: blocks [0,OUTB) outside rows, [OUTB,OUTB+CTRB) center pairs ----
__global__ void pass1(const float* __restrict__ pos, const float* __restrict__ box,
                      const int* __restrict__ shifts, long long P) {
    __shared__ float spx[NA], spy[NA], spz[NA];
    int tid = threadIdx.x;
    for (int k = tid; k < NA; k += 256) {
        spx[k] = pos[3 * k + 0];
        spy[k] = pos[3 * k + 1];
        spz[k] = pos[3 * k + 2];
    }
    __syncthreads();
    if (blockIdx.x < OUTB) {
        int rowBase = blockIdx.x * 8;
        #pragma unroll 1
        for (int rr = 0; rr < 8; rr++) {
            int row = rowBase + rr;
            int s = row >> 10, i = row & 1023;
            float s0 = (float)shifts[3 * s + 0];
            float s1 = (float)shifts[3 * s + 1];
            float s2 = (float)shifts[3 * s + 2];
            float svx = s0 * box[0] + s1 * box[3] + s2 * box[6];
            float svy = s0 * box[1] + s1 * box[4] + s2 * box[7];
            float svz = s0 * box[2] + s1 * box[5] + s2 * box[8];
            float pix = spx[i], piy = spy[i], piz = spz[i];
            int t2base = PCI + (row << 10);
            #pragma unroll
            for (int c = 0; c < 4; c++) {
                int j = c * 256 + tid;
                float dx = __fadd_rn(__fsub_rn(pix, spx[j]), svx);
                float dy = __fadd_rn(__fsub_rn(piy, spy[j]), svy);
                float dz = __fadd_rn(__fsub_rn(piz, spz[j]), svz);
                float r2 = __fadd_rn(__fadd_rn(__fmul_rn(dx, dx), __fmul_rn(dy, dy)),
                                     __fmul_rn(dz, dz));
                bool valid = __fsqrt_rn(r2) < CUT;
                unsigned b = __ballot_sync(0xFFFFFFFFu, valid);
                if ((tid & 31) == 0)
                    d_mask[(t2base >> 5) + c * 8 + (tid >> 5)] = b;
                if (valid) {
                    unsigned t2 = (unsigned)(t2base + j);
                    int sl = atomicAdd(&d_atomCount[i], 1);
                    if (sl < MAXB) d_bucket[i * MAXB + sl] = t2;
                    int s2a = atomicAdd(&d_atomCount[j], 1);
                    if (s2a < MAXB) d_bucket[j * MAXB + s2a] = t2 + (unsigned)P;
                }
            }
        }
    } else {
        int cb = blockIdx.x - OUTB;
        #pragma unroll 1
        for (int c = 0; c < 32; c++) {
            int t2 = cb * 8192 + c * 256 + tid;
            bool valid = false;
            int i0 = 0, j0 = 0;
            if (t2 < PCI) {
                decodeCenter(t2, i0, j0);
                float dx = __fsub_rn(spx[i0], spx[j0]);
                float dy = __fsub_rn(spy[i0], spy[j0]);
                float dz = __fsub_rn(spz[i0], spz[j0]);
                float r2 = __fadd_rn(__fadd_rn(__fmul_rn(dx, dx), __fmul_rn(dy, dy)),
                                     __fmul_rn(dz, dz));
                valid = __fsqrt_rn(r2) < CUT;
            }
            unsigned b = __ballot_sync(0xFFFFFFFFu, valid);
            int wb = cb * 256 + c * 8 + (tid >> 5);
            if ((tid & 31) == 0 && wb < (PCI >> 5))
                d_mask[wb] = b;
            if (valid) {
                int sl = atomicAdd(&d_atomCount[i0], 1);
                if (sl < MAXB) d_bucket[i0 * MAXB + sl] = (unsigned)t2;
                int s2a = atomicAdd(&d_atomCount[j0], 1);
                if (s2a < MAXB) d_bucket[j0 * MAXB + s2a] = (unsigned)(t2 + P);
            }
        }
    }
}

// ---- shuffle-based scans ----
__global__ void scanA(int W) {
    __shared__ int wsum[32];
    int tid = threadIdx.x, lane = tid & 31, wid = tid >> 5;
    int w = blockIdx.x * 1024 + tid;
    int v = (w < W) ? __popc(d_mask[w]) : 0;
    int x = v;
    #pragma unroll
    for (int o = 1; o < 32; o <<= 1) {
        int y = __shfl_up_sync(0xFFFFFFFFu, x, o);
        if (lane >= o) x += y;
    }
    if (lane == 31) wsum[wid] = x;
    __syncthreads();
    if (wid == 0) {
        int y = wsum[lane];
        #pragma unroll
        for (int o = 1; o < 32; o <<= 1) {
            int z = __shfl_up_sync(0xFFFFFFFFu, y, o);
            if (lane >= o) y += z;
        }
        wsum[lane] = y;
    }
    __syncthreads();
    int base = wid ? wsum[wid - 1] : 0;
    if (w < W) d_wpre[w] = base + x - v;
    if (tid == 0) d_bsums[blockIdx.x] = wsum[31];
}

__global__ void scanB(int nb) {
    __shared__ int wsum[32];
    int tid = threadIdx.x, lane = tid & 31, wid = tid >> 5;
    int v = (tid < nb) ? d_bsums[tid] : 0;
    int x = v;
    #pragma unroll
    for (int o = 1; o < 32; o <<= 1) {
        int y = __shfl_up_sync(0xFFFFFFFFu, x, o);
        if (lane >= o) x += y;
    }
    if (lane == 31) wsum[wid] = x;
    __syncthreads();
    if (wid == 0) {
        int y = wsum[lane];
        #pragma unroll
        for (int o = 1; o < 32; o <<= 1) {
            int z = __shfl_up_sync(0xFFFFFFFFu, y, o);
            if (lane >= o) y += z;
        }
        wsum[lane] = y;
    }
    __syncthreads();
    int base = wid ? wsum[wid - 1] : 0;
    if (tid < nb) d_bpre[tid] = base + x - v;
    if (tid == 0) { d_Vh = wsum[31]; d_V = 2 * wsum[31]; }
    __syncthreads();
    // atom exclusive scan
    int a = d_atomCount[tid];
    int xa = a;
    #pragma unroll
    for (int o = 1; o < 32; o <<= 1) {
        int y = __shfl_up_sync(0xFFFFFFFFu, xa, o);
        if (lane >= o) xa += y;
    }
    __syncthreads();
    if (lane == 31) wsum[wid] = xa;
    __syncthreads();
    if (wid == 0) {
        int y = wsum[lane];
        #pragma unroll
        for (int o = 1; o < 32; o <<= 1) {
            int z = __shfl_up_sync(0xFFFFFFFFu, y, o);
            if (lane >= o) y += z;
        }
        wsum[lane] = y;
    }
    __syncthreads();
    int basea = wid ? wsum[wid - 1] : 0;
    d_atomBase[tid] = basea + xa - a;
}

// ---- fused bulk writer: zero-fill | idx (both halves) | valid scatter ----
__global__ void writeBulk(const float* __restrict__ box, const int* __restrict__ shifts,
                          long long P, long long TWOP, float* __restrict__ out) {
    __shared__ unsigned sb[MAXB];
    int b = blockIdx.x, tid = threadIdx.x;
    if (b < NZ) {
        // zero offsets [2*TWOP, 5*TWOP) and valid [5*TWOP, 6*TWOP): TWOP float4s
        float4* p = (float4*)(out + 2 * TWOP);
        long long stride = (long long)NZ * 256;
        float4 z = make_float4(0.f, 0.f, 0.f, 0.f);
        for (long long i = (long long)b * 256 + tid; i < TWOP; i += stride)
            p[i] = z;
    } else if (b < NZ + NI) {
        int V = d_V, Vh = d_Vh;
        long long roff = P - (long long)Vh;
        long long stride = (long long)NI * 256;
        for (long long tl = (long long)(b - NZ) * 256 + tid; tl < P; tl += stride) {
            int t2 = (int)tl;
            unsigned w = (unsigned)t2 >> 5;
            unsigned word = d_mask[w];
            unsigned lanebit = 1u << (t2 & 31);
            if (word & lanebit) continue;
            int before = d_bpre[w >> 10] + d_wpre[w] + __popc(word & (lanebit - 1u));
            long long r1 = (long long)V + tl - before;
            long long r2 = r1 + roff;
            int bi, bj;
            if (t2 >= PCI) {
                unsigned u = (unsigned)(t2 - PCI);
                bi = (int)((u >> 10) & 1023u);
                bj = (int)(u & 1023u);
            } else {
                decodeCenter(t2, bi, bj);
            }
            float fbi = (float)bi, fbj = (float)bj;
            out[r1] = fbi;
            out[TWOP + r1] = fbj;
            out[r2] = fbj;
            out[TWOP + r2] = fbi;
        }
    } else {
        int v = b - NZ - NI;            // atom id
        int c = d_atomCount[v];
        if (c > MAXB) c = MAXB;
        for (int k = tid; k < c; k += 256) sb[k] = d_bucket[v * MAXB + k];
        __syncthreads();
        if (tid >= c) return;
        unsigned te = sb[tid];
        int rank = 0;
        for (int k = 0; k < c; k++) rank += (sb[k] < te) ? 1 : 0;
        long long r = (long long)d_atomBase[v] + rank;

        long long t = (long long)te;
        bool second = t >= P;
        int t2 = (int)(second ? t - P : t);
        int i0, j0, s;
        if (t2 >= PCI) {
            unsigned u = (unsigned)(t2 - PCI);
            s = (int)(u >> 20);
            i0 = (int)((u >> 10) & 1023u);
            j0 = (int)(u & 1023u);
        } else {
            s = -1;
            decodeCenter(t2, i0, j0);
        }
        int bi = second ? j0 : i0;
        int bj = second ? i0 : j0;
        float o0 = 0.f, o1 = 0.f, o2 = 0.f;
        if (s >= 0) {
            float sgn = second ? 1.0f : -1.0f;
            float s0 = sgn * (float)shifts[3 * s + 0];
            float s1 = sgn * (float)shifts[3 * s + 1];
            float s2 = sgn * (float)shifts[3 * s + 2];
            o0 = s0 * box[0] + s1 * box[3] + s2 * box[6];
            o1 = s0 * box[1] + s1 * box[4] + s2 * box[7];
            o2 = s0 * box[2] + s1 * box[5] + s2 * box[8];
        }
        out[r] = (float)bi;
        out[TWOP + r] = (float)bj;
        long long ob = 2 * TWOP + 3 * r;
        out[ob + 0] = o0;
        out[ob + 1] = o1;
        out[ob + 2] = o2;
        out[5 * TWOP + r] = 1.0f;
    }
}

extern "C" void kernel_launch(void* const* d_in, const int* in_sizes, int n_in,
                              void* d_out, int out_size) {
    const float* pos  = (const float*)d_in[0];
    const float* box  = (const float*)d_in[1];
    const int* shifts = (const int*)d_in[2];

    long long TWOP = (long long)out_size / 6;    // 28,310,528
    long long P = TWOP / 2;                      // 14,155,264
    int W = (int)(P / 32);                       // 442,352
    int nScanBlocks = (W + 1023) / 1024;         // 432
    float* out = (float*)d_out;

    initK<<<1, NA>>>();
    pass1<<<OUTB + CTRB, 256>>>(pos, box, shifts, P);
    scanA<<<nScanBlocks, 1024>>>(W);
    scanB<<<1, 1024>>>(nScanBlocks);
    writeBulk<<<NZ + NI + NA, 256>>>(box, shifts, P, TWOP, out);
}